// round 1
// baseline (speedup 1.0000x reference)
#include <cuda_runtime.h>
#include <math.h>

#define DM    1024
#define NH    16
#define HD    64
#define BATCH 2
#define SEQ   2048
#define MROWS (BATCH*SEQ)      // 4096

// Scratch (device globals — no allocation allowed)
__device__ float g_q [MROWS*DM];
__device__ float g_k [MROWS*DM];   // pre-scaled by 1/sqrt(HD)
__device__ float g_v [MROWS*DM];
__device__ float g_c1[MROWS*DM];
__device__ float g_c2[MROWS*DM];

// ---------------------------------------------------------------------------
// GEMM:  C[M,N] = A[M,K] @ B[N,K]^T + bias[N]
// MODE 0: plain write to C
// MODE 1: qkv scatter into qo/ko/vo (N must be 3*DM); ko scaled by 0.125
// Requires M%64==0, N%64==0, K%16==0.
// ---------------------------------------------------------------------------
template<int MODE>
__global__ __launch_bounds__(256)
void gemm_bias_kernel(const float* __restrict__ A, const float* __restrict__ Bw,
                      const float* __restrict__ bias, float* __restrict__ C,
                      int M, int N, int K,
                      float* __restrict__ qo, float* __restrict__ ko,
                      float* __restrict__ vo)
{
    __shared__ float As[16][68];   // As[k][m]
    __shared__ float Bs[16][68];   // Bs[k][n]

    const int t  = threadIdx.x;
    const int tx = t & 15, ty = t >> 4;
    const int bm = blockIdx.y * 64, bn = blockIdx.x * 64;
    const int lrow = t >> 2, lc4 = (t & 3) * 4;   // 64 rows x 16 cols loader

    float acc[4][4];
    #pragma unroll
    for (int i = 0; i < 4; i++)
        #pragma unroll
        for (int j = 0; j < 4; j++) acc[i][j] = 0.f;

    const float* Arow = A  + (size_t)(bm + lrow) * K + lc4;
    const float* Brow = Bw + (size_t)(bn + lrow) * K + lc4;

    for (int k0 = 0; k0 < K; k0 += 16) {
        float4 av = *(const float4*)(Arow + k0);
        float4 bv = *(const float4*)(Brow + k0);
        As[lc4+0][lrow] = av.x; As[lc4+1][lrow] = av.y;
        As[lc4+2][lrow] = av.z; As[lc4+3][lrow] = av.w;
        Bs[lc4+0][lrow] = bv.x; Bs[lc4+1][lrow] = bv.y;
        Bs[lc4+2][lrow] = bv.z; Bs[lc4+3][lrow] = bv.w;
        __syncthreads();

        #pragma unroll
        for (int kk = 0; kk < 16; kk++) {
            float4 a4 = *(const float4*)&As[kk][4*ty];
            float4 b4 = *(const float4*)&Bs[kk][4*tx];
            float aa[4] = {a4.x, a4.y, a4.z, a4.w};
            float bb[4] = {b4.x, b4.y, b4.z, b4.w};
            #pragma unroll
            for (int i = 0; i < 4; i++)
                #pragma unroll
                for (int j = 0; j < 4; j++)
                    acc[i][j] = fmaf(aa[i], bb[j], acc[i][j]);
        }
        __syncthreads();
    }

    #pragma unroll
    for (int i = 0; i < 4; i++) {
        const int r = bm + 4*ty + i;
        #pragma unroll
        for (int j = 0; j < 4; j++) {
            const int c = bn + 4*tx + j;
            float val = acc[i][j] + bias[c];
            if (MODE == 0) {
                C[(size_t)r * N + c] = val;
            } else {
                const int g   = c >> 10;        // 0=q,1=k,2=v
                const int rem = c & 1023;
                if (g == 1) val *= 0.125f;      // fold 1/sqrt(64) into K
                float* dst = (g == 0) ? qo : (g == 1) ? ko : vo;
                dst[(size_t)r * DM + rem] = val;
            }
        }
    }
}

// ---------------------------------------------------------------------------
// Causal flash attention, one CTA per (q-tile of 64 rows, head, batch).
// K buffer is pre-scaled. Online softmax, fp32 throughout.
// ---------------------------------------------------------------------------
#define ATTN_SMEM (4 * 64 * 68 * 4)   // Qs,Ks,Vs,Ps tiles, stride 68

__global__ __launch_bounds__(256)
void attn_kernel(const float* __restrict__ Qb, const float* __restrict__ Kb,
                 const float* __restrict__ Vb, float* __restrict__ Ob)
{
    extern __shared__ float sm[];
    float (*Qs)[68] = (float(*)[68])(sm);              // Qs[d][r]
    float (*Ks)[68] = (float(*)[68])(sm + 64*68);      // Ks[d][t]
    float (*Vs)[68] = (float(*)[68])(sm + 2*64*68);    // Vs[t][d]
    float (*Ps)[68] = (float(*)[68])(sm + 3*64*68);    // Ps[r][t]

    const int qt = blockIdx.x, h = blockIdx.y, b = blockIdx.z;
    const int t  = threadIdx.x;
    const int tx = t & 15, ty = t >> 4;
    const int lrow = t >> 4, lc4 = (t & 15) * 4;       // 64x64 tile loader

    const size_t base = (size_t)b * SEQ * DM + (size_t)h * HD;
    const float* Qg = Qb + base + (size_t)(qt * 64) * DM;

    // Load Q tile transposed: Qs[d][r]
    #pragma unroll
    for (int it = 0; it < 4; it++) {
        const int r = lrow + it * 16;
        float4 qv = *(const float4*)(Qg + (size_t)r * DM + lc4);
        Qs[lc4+0][r] = qv.x; Qs[lc4+1][r] = qv.y;
        Qs[lc4+2][r] = qv.z; Qs[lc4+3][r] = qv.w;
    }

    const float NEG_INF = __int_as_float(0xff800000);
    float m_run[4], l_run[4], acc[4][4];
    #pragma unroll
    for (int i = 0; i < 4; i++) {
        m_run[i] = NEG_INF; l_run[i] = 0.f;
        #pragma unroll
        for (int j = 0; j < 4; j++) acc[i][j] = 0.f;
    }
    __syncthreads();

    for (int kt = 0; kt <= qt; kt++) {
        const float* Kg = Kb + base + (size_t)(kt * 64) * DM;
        const float* Vg = Vb + base + (size_t)(kt * 64) * DM;

        #pragma unroll
        for (int it = 0; it < 4; it++) {
            const int r = lrow + it * 16;
            float4 kv = *(const float4*)(Kg + (size_t)r * DM + lc4);
            Ks[lc4+0][r] = kv.x; Ks[lc4+1][r] = kv.y;
            Ks[lc4+2][r] = kv.z; Ks[lc4+3][r] = kv.w;
            float4 vv = *(const float4*)(Vg + (size_t)r * DM + lc4);
            *(float4*)&Vs[r][lc4] = vv;
        }
        __syncthreads();

        // S = Q @ K^T  (64x64 tile; thread owns 4x4)
        float s[4][4];
        #pragma unroll
        for (int i = 0; i < 4; i++)
            #pragma unroll
            for (int j = 0; j < 4; j++) s[i][j] = 0.f;

        #pragma unroll
        for (int d = 0; d < 64; d++) {
            float4 a4 = *(const float4*)&Qs[d][4*ty];
            float4 b4 = *(const float4*)&Ks[d][4*tx];
            float aa[4] = {a4.x, a4.y, a4.z, a4.w};
            float bb[4] = {b4.x, b4.y, b4.z, b4.w};
            #pragma unroll
            for (int i = 0; i < 4; i++)
                #pragma unroll
                for (int j = 0; j < 4; j++)
                    s[i][j] = fmaf(aa[i], bb[j], s[i][j]);
        }

        // Causal mask (only the diagonal tile needs it)
        if (kt == qt) {
            #pragma unroll
            for (int i = 0; i < 4; i++)
                #pragma unroll
                for (int j = 0; j < 4; j++)
                    if (4*tx + j > 4*ty + i) s[i][j] = NEG_INF;
        }

        // Online softmax per row; row r=4*ty+i spans the 16 tx lanes (half-warp)
        #pragma unroll
        for (int i = 0; i < 4; i++) {
            float mx = fmaxf(fmaxf(s[i][0], s[i][1]), fmaxf(s[i][2], s[i][3]));
            #pragma unroll
            for (int o = 8; o; o >>= 1)
                mx = fmaxf(mx, __shfl_xor_sync(0xffffffffu, mx, o));
            const float m_new = fmaxf(m_run[i], mx);
            const float alpha = __expf(m_run[i] - m_new);
            float rs = 0.f;
            #pragma unroll
            for (int j = 0; j < 4; j++) { s[i][j] = __expf(s[i][j] - m_new); rs += s[i][j]; }
            #pragma unroll
            for (int o = 8; o; o >>= 1)
                rs += __shfl_xor_sync(0xffffffffu, rs, o);
            l_run[i] = l_run[i] * alpha + rs;
            m_run[i] = m_new;
            #pragma unroll
            for (int j = 0; j < 4; j++) acc[i][j] *= alpha;
            *(float4*)&Ps[4*ty + i][4*tx] = make_float4(s[i][0], s[i][1], s[i][2], s[i][3]);
        }
        __syncthreads();

        // O += P @ V
        #pragma unroll 8
        for (int tt = 0; tt < 64; tt++) {
            float4 v4 = *(const float4*)&Vs[tt][4*tx];
            float vv[4] = {v4.x, v4.y, v4.z, v4.w};
            float pa[4];
            #pragma unroll
            for (int i = 0; i < 4; i++) pa[i] = Ps[4*ty + i][tt];
            #pragma unroll
            for (int i = 0; i < 4; i++)
                #pragma unroll
                for (int j = 0; j < 4; j++)
                    acc[i][j] = fmaf(pa[i], vv[j], acc[i][j]);
        }
        __syncthreads();
    }

    float* Og = Ob + base + (size_t)(qt * 64) * DM;
    #pragma unroll
    for (int i = 0; i < 4; i++) {
        const float inv_l = 1.0f / l_run[i];
        float4 o4 = make_float4(acc[i][0]*inv_l, acc[i][1]*inv_l,
                                acc[i][2]*inv_l, acc[i][3]*inv_l);
        *(float4*)(Og + (size_t)(4*ty + i) * DM + 4*tx) = o4;
    }
}

// ---------------------------------------------------------------------------
extern "C" void kernel_launch(void* const* d_in, const int* in_sizes, int n_in,
                              void* d_out, int out_size)
{
    const float* x  = (const float*)d_in[0];
    const float* Ww = (const float*)d_in[1];
    const float* Wb = (const float*)d_in[2];
    const float* Ow = (const float*)d_in[3];
    const float* Ob = (const float*)d_in[4];
    float* out = (float*)d_out;

    float *q, *k, *v, *c1, *c2;
    cudaGetSymbolAddress((void**)&q,  g_q);
    cudaGetSymbolAddress((void**)&k,  g_k);
    cudaGetSymbolAddress((void**)&v,  g_v);
    cudaGetSymbolAddress((void**)&c1, g_c1);
    cudaGetSymbolAddress((void**)&c2, g_c2);

    cudaFuncSetAttribute(attn_kernel,
                         cudaFuncAttributeMaxDynamicSharedMemorySize, ATTN_SMEM);

    // 1) QKV projection + bias, scatter into q/k/v (k pre-scaled)
    dim3 g1(3*DM/64, MROWS/64);
    gemm_bias_kernel<1><<<g1, 256>>>(x, Ww, Wb, nullptr,
                                     MROWS, 3*DM, DM, q, k, v);

    // 2-4) repeated causal attention (k,v reused; ping-pong contexts)
    dim3 ga(SEQ/64, NH, BATCH);
    attn_kernel<<<ga, 256, ATTN_SMEM>>>(q,  k, v, c1);
    attn_kernel<<<ga, 256, ATTN_SMEM>>>(c1, k, v, c2);
    attn_kernel<<<ga, 256, ATTN_SMEM>>>(c2, k, v, c1);

    // 5) output projection + bias
    dim3 g2(DM/64, MROWS/64);
    gemm_bias_kernel<0><<<g2, 256>>>(c1, Ow, Ob, out,
                                     MROWS, DM, DM, nullptr, nullptr, nullptr);
}

// round 2
// speedup vs baseline: 3.0908x; 3.0908x over previous
#include <cuda_runtime.h>
#include <math.h>

#define DM    1024
#define NH    16
#define HD    64
#define BATCH 2
#define SEQ   2048
#define MROWS (BATCH*SEQ)      // 4096

// Scratch (device globals — no allocation allowed)
__device__ float g_q [MROWS*DM];
__device__ float g_k [MROWS*DM];   // pre-scaled by 1/sqrt(HD)
__device__ float g_v [MROWS*DM];
__device__ float g_c1[MROWS*DM];
__device__ float g_c2[MROWS*DM];

__device__ __forceinline__ unsigned f2tf(float f) {
    unsigned u;
    asm("cvt.rna.tf32.f32 %0, %1;" : "=r"(u) : "f"(f));
    return u;
}

__device__ __forceinline__ void mma8(float* d, const unsigned* a,
                                     unsigned b0, unsigned b1) {
    asm volatile(
        "mma.sync.aligned.m16n8k8.row.col.f32.tf32.tf32.f32 "
        "{%0,%1,%2,%3}, {%4,%5,%6,%7}, {%8,%9}, {%0,%1,%2,%3};"
        : "+f"(d[0]), "+f"(d[1]), "+f"(d[2]), "+f"(d[3])
        : "r"(a[0]), "r"(a[1]), "r"(a[2]), "r"(a[3]), "r"(b0), "r"(b1));
}

// ---------------------------------------------------------------------------
// TF32 tensor-core GEMM: C[M,N] = A[M,K] @ Bw[N,K]^T + bias[N]
// MODE 0: plain write; MODE 1: qkv scatter (k scaled by 0.125)
// CTA tile 128x128, 256 threads (8 warps 4x2), warp tile 32x64, kc=16.
// ---------------------------------------------------------------------------
template<int MODE>
__global__ __launch_bounds__(256)
void gemm_tc(const float* __restrict__ A, const float* __restrict__ Bw,
             const float* __restrict__ bias, float* __restrict__ C,
             int M, int N, int K,
             float* __restrict__ qo, float* __restrict__ ko,
             float* __restrict__ vo)
{
    __shared__ unsigned As[128][20];
    __shared__ unsigned Bs[128][20];

    const int tid = threadIdx.x;
    const int wid = tid >> 5, lane = tid & 31;
    const int lg = lane >> 2, la3 = lane & 3;
    const int wm = wid & 3, wn = wid >> 2;          // warp grid 4x2
    const int bm = blockIdx.y * 128, bn = blockIdx.x * 128;

    float acc[2][8][4];
    #pragma unroll
    for (int mt = 0; mt < 2; mt++)
        #pragma unroll
        for (int nt = 0; nt < 8; nt++)
            #pragma unroll
            for (int i = 0; i < 4; i++) acc[mt][nt][i] = 0.f;

    const int lrow = tid >> 2, lcol = (tid & 3) * 4;   // 64 rows x 16 cols
    const float* Ap = A  + (size_t)(bm + lrow) * K + lcol;
    const float* Bp = Bw + (size_t)(bn + lrow) * K + lcol;

    for (int k0 = 0; k0 < K; k0 += 16) {
        float4 a0 = *(const float4*)(Ap + k0);
        float4 a1 = *(const float4*)(Ap + (size_t)64 * K + k0);
        float4 b0 = *(const float4*)(Bp + k0);
        float4 b1 = *(const float4*)(Bp + (size_t)64 * K + k0);
        __syncthreads();
        *(uint4*)&As[lrow   ][lcol] = make_uint4(f2tf(a0.x), f2tf(a0.y), f2tf(a0.z), f2tf(a0.w));
        *(uint4*)&As[lrow+64][lcol] = make_uint4(f2tf(a1.x), f2tf(a1.y), f2tf(a1.z), f2tf(a1.w));
        *(uint4*)&Bs[lrow   ][lcol] = make_uint4(f2tf(b0.x), f2tf(b0.y), f2tf(b0.z), f2tf(b0.w));
        *(uint4*)&Bs[lrow+64][lcol] = make_uint4(f2tf(b1.x), f2tf(b1.y), f2tf(b1.z), f2tf(b1.w));
        __syncthreads();

        #pragma unroll
        for (int ks = 0; ks < 2; ks++) {
            unsigned af[2][4], bf[8][2];
            #pragma unroll
            for (int mt = 0; mt < 2; mt++) {
                const int r = wm * 32 + mt * 16 + lg;
                af[mt][0] = As[r    ][ks * 8 + la3];
                af[mt][1] = As[r + 8][ks * 8 + la3];
                af[mt][2] = As[r    ][ks * 8 + la3 + 4];
                af[mt][3] = As[r + 8][ks * 8 + la3 + 4];
            }
            #pragma unroll
            for (int nt = 0; nt < 8; nt++) {
                const int n = wn * 64 + nt * 8 + lg;
                bf[nt][0] = Bs[n][ks * 8 + la3];
                bf[nt][1] = Bs[n][ks * 8 + la3 + 4];
            }
            #pragma unroll
            for (int mt = 0; mt < 2; mt++)
                #pragma unroll
                for (int nt = 0; nt < 8; nt++)
                    mma8(acc[mt][nt], af[mt], bf[nt][0], bf[nt][1]);
        }
    }

    #pragma unroll
    for (int mt = 0; mt < 2; mt++)
        #pragma unroll
        for (int nt = 0; nt < 8; nt++)
            #pragma unroll
            for (int i = 0; i < 4; i++) {
                const int row = bm + wm * 32 + mt * 16 + lg + (i >> 1) * 8;
                const int col = bn + wn * 64 + nt * 8 + 2 * la3 + (i & 1);
                float val = acc[mt][nt][i] + bias[col];
                if (MODE == 0) {
                    C[(size_t)row * N + col] = val;
                } else {
                    const int g   = col >> 10;
                    const int rem = col & 1023;
                    if (g == 1) val *= 0.125f;
                    float* dst = (g == 0) ? qo : (g == 1) ? ko : vo;
                    dst[(size_t)row * DM + rem] = val;
                }
            }
}

// ---------------------------------------------------------------------------
// TF32 tensor-core causal flash attention.
// CTA: 128 threads (4 warps), 64-row Q tile, head dim 64.
// Q fragments register-resident; K/V staged per kv-tile; P via per-warp smem.
// ---------------------------------------------------------------------------
#define KP 68   // pad for Ks/Ps: bank = lg*4+la3 -> conflict-free frag loads
#define VP 72   // pad for Vs:    bank = la3*8+lg -> conflict-free PV-B loads
#define ATTN_SMEM ((64*KP + 64*VP + 64*KP) * 4)

__global__ __launch_bounds__(128)
void attn_tc(const float* __restrict__ Qb, const float* __restrict__ Kb,
             const float* __restrict__ Vb, float* __restrict__ Ob)
{
    extern __shared__ unsigned sm[];
    unsigned (*Ks)[KP] = (unsigned(*)[KP])sm;               // [64][68] Ks[kv][d]
    unsigned (*Vs)[VP] = (unsigned(*)[VP])(sm + 64*KP);     // [64][72] Vs[kv][d]
    unsigned (*Ps)[KP] = (unsigned(*)[KP])(sm + 64*KP + 64*VP); // [64][68] P[q][kv]

    const int qt = (int)gridDim.x - 1 - (int)blockIdx.x;    // long rows first
    const int h = blockIdx.y, b = blockIdx.z;
    const int tid = threadIdx.x, wid = tid >> 5, lane = tid & 31;
    const int lg = lane >> 2, la3 = lane & 3;
    const int wb = wid * 16;
    const float NEG_INF = __int_as_float(0xff800000);

    const size_t base = (size_t)b * SEQ * DM + (size_t)h * HD;

    // ---- Stage Q through Ks, load fragments once ----
    const float* Qg = Qb + base + (size_t)(qt * 64) * DM;
    #pragma unroll
    for (int i = 0; i < 8; i++) {
        const int linear = i * 512 + tid * 4;      // 0..4095
        const int r = linear >> 6, c = linear & 63;
        float4 v = *(const float4*)(Qg + (size_t)r * DM + c);
        *(uint4*)&Ks[r][c] = make_uint4(f2tf(v.x), f2tf(v.y), f2tf(v.z), f2tf(v.w));
    }
    __syncthreads();
    unsigned Qf[8][4];
    #pragma unroll
    for (int k8 = 0; k8 < 8; k8++) {
        Qf[k8][0] = Ks[wb + lg    ][k8 * 8 + la3];
        Qf[k8][1] = Ks[wb + lg + 8][k8 * 8 + la3];
        Qf[k8][2] = Ks[wb + lg    ][k8 * 8 + la3 + 4];
        Qf[k8][3] = Ks[wb + lg + 8][k8 * 8 + la3 + 4];
    }
    __syncthreads();

    float m0 = NEG_INF, m1 = NEG_INF, l0 = 0.f, l1 = 0.f;
    float O[8][4];
    #pragma unroll
    for (int nt = 0; nt < 8; nt++)
        #pragma unroll
        for (int i = 0; i < 4; i++) O[nt][i] = 0.f;

    for (int kt = 0; kt <= qt; kt++) {
        const float* Kg = Kb + base + (size_t)(kt * 64) * DM;
        const float* Vg = Vb + base + (size_t)(kt * 64) * DM;
        #pragma unroll
        for (int i = 0; i < 8; i++) {
            const int linear = i * 512 + tid * 4;
            const int r = linear >> 6, c = linear & 63;
            float4 kv = *(const float4*)(Kg + (size_t)r * DM + c);
            *(uint4*)&Ks[r][c] = make_uint4(f2tf(kv.x), f2tf(kv.y), f2tf(kv.z), f2tf(kv.w));
            float4 vv = *(const float4*)(Vg + (size_t)r * DM + c);
            *(uint4*)&Vs[r][c] = make_uint4(f2tf(vv.x), f2tf(vv.y), f2tf(vv.z), f2tf(vv.w));
        }
        __syncthreads();

        // ---- S = Q @ K^T (16x64 per warp) ----
        float S[8][4];
        #pragma unroll
        for (int nt = 0; nt < 8; nt++)
            #pragma unroll
            for (int i = 0; i < 4; i++) S[nt][i] = 0.f;

        #pragma unroll
        for (int k8 = 0; k8 < 8; k8++)
            #pragma unroll
            for (int nt = 0; nt < 8; nt++) {
                unsigned b0 = Ks[nt * 8 + lg][k8 * 8 + la3];
                unsigned b1 = Ks[nt * 8 + lg][k8 * 8 + la3 + 4];
                mma8(S[nt], Qf[k8], b0, b1);
            }

        // ---- Causal mask (diagonal tile only) ----
        if (kt == qt) {
            #pragma unroll
            for (int nt = 0; nt < 8; nt++) {
                const int c0 = nt * 8 + 2 * la3;
                const int r0 = wb + lg, r1 = r0 + 8;
                if (c0     > r0) S[nt][0] = NEG_INF;
                if (c0 + 1 > r0) S[nt][1] = NEG_INF;
                if (c0     > r1) S[nt][2] = NEG_INF;
                if (c0 + 1 > r1) S[nt][3] = NEG_INF;
            }
        }

        // ---- Online softmax (rows r0=wb+lg, r1=wb+lg+8; 4-lane quads) ----
        float mx0 = NEG_INF, mx1 = NEG_INF;
        #pragma unroll
        for (int nt = 0; nt < 8; nt++) {
            mx0 = fmaxf(mx0, fmaxf(S[nt][0], S[nt][1]));
            mx1 = fmaxf(mx1, fmaxf(S[nt][2], S[nt][3]));
        }
        mx0 = fmaxf(mx0, __shfl_xor_sync(0xffffffffu, mx0, 1));
        mx0 = fmaxf(mx0, __shfl_xor_sync(0xffffffffu, mx0, 2));
        mx1 = fmaxf(mx1, __shfl_xor_sync(0xffffffffu, mx1, 1));
        mx1 = fmaxf(mx1, __shfl_xor_sync(0xffffffffu, mx1, 2));
        const float mn0 = fmaxf(m0, mx0), mn1 = fmaxf(m1, mx1);
        const float al0 = __expf(m0 - mn0), al1 = __expf(m1 - mn1);
        float rs0 = 0.f, rs1 = 0.f;
        #pragma unroll
        for (int nt = 0; nt < 8; nt++) {
            S[nt][0] = __expf(S[nt][0] - mn0);
            S[nt][1] = __expf(S[nt][1] - mn0);
            S[nt][2] = __expf(S[nt][2] - mn1);
            S[nt][3] = __expf(S[nt][3] - mn1);
            rs0 += S[nt][0] + S[nt][1];
            rs1 += S[nt][2] + S[nt][3];
        }
        rs0 += __shfl_xor_sync(0xffffffffu, rs0, 1);
        rs0 += __shfl_xor_sync(0xffffffffu, rs0, 2);
        rs1 += __shfl_xor_sync(0xffffffffu, rs1, 1);
        rs1 += __shfl_xor_sync(0xffffffffu, rs1, 2);
        l0 = l0 * al0 + rs0;  m0 = mn0;
        l1 = l1 * al1 + rs1;  m1 = mn1;
        #pragma unroll
        for (int nt = 0; nt < 8; nt++) {
            O[nt][0] *= al0;  O[nt][1] *= al0;
            O[nt][2] *= al1;  O[nt][3] *= al1;
        }

        // ---- P -> per-warp-private smem (layout fixup for A operand) ----
        #pragma unroll
        for (int nt = 0; nt < 8; nt++) {
            *(uint2*)&Ps[wb + lg    ][nt * 8 + 2 * la3] =
                make_uint2(f2tf(S[nt][0]), f2tf(S[nt][1]));
            *(uint2*)&Ps[wb + lg + 8][nt * 8 + 2 * la3] =
                make_uint2(f2tf(S[nt][2]), f2tf(S[nt][3]));
        }
        __syncwarp();
        unsigned Pf[8][4];
        #pragma unroll
        for (int k8 = 0; k8 < 8; k8++) {
            Pf[k8][0] = Ps[wb + lg    ][k8 * 8 + la3];
            Pf[k8][1] = Ps[wb + lg + 8][k8 * 8 + la3];
            Pf[k8][2] = Ps[wb + lg    ][k8 * 8 + la3 + 4];
            Pf[k8][3] = Ps[wb + lg + 8][k8 * 8 + la3 + 4];
        }

        // ---- O += P @ V ----
        #pragma unroll
        for (int k8 = 0; k8 < 8; k8++)
            #pragma unroll
            for (int nt = 0; nt < 8; nt++) {
                unsigned b0 = Vs[k8 * 8 + la3    ][nt * 8 + lg];
                unsigned b1 = Vs[k8 * 8 + la3 + 4][nt * 8 + lg];
                mma8(O[nt], Pf[k8], b0, b1);
            }
        __syncthreads();
    }

    // ---- Epilogue ----
    float* Og = Ob + base + (size_t)(qt * 64) * DM;
    const float il0 = 1.0f / l0, il1 = 1.0f / l1;
    #pragma unroll
    for (int nt = 0; nt < 8; nt++) {
        const int col = nt * 8 + 2 * la3;
        *(float2*)(Og + (size_t)(wb + lg    ) * DM + col) =
            make_float2(O[nt][0] * il0, O[nt][1] * il0);
        *(float2*)(Og + (size_t)(wb + lg + 8) * DM + col) =
            make_float2(O[nt][2] * il1, O[nt][3] * il1);
    }
}

// ---------------------------------------------------------------------------
extern "C" void kernel_launch(void* const* d_in, const int* in_sizes, int n_in,
                              void* d_out, int out_size)
{
    const float* x  = (const float*)d_in[0];
    const float* Ww = (const float*)d_in[1];
    const float* Wb = (const float*)d_in[2];
    const float* Ow = (const float*)d_in[3];
    const float* Ob = (const float*)d_in[4];
    float* out = (float*)d_out;

    float *q, *k, *v, *c1, *c2;
    cudaGetSymbolAddress((void**)&q,  g_q);
    cudaGetSymbolAddress((void**)&k,  g_k);
    cudaGetSymbolAddress((void**)&v,  g_v);
    cudaGetSymbolAddress((void**)&c1, g_c1);
    cudaGetSymbolAddress((void**)&c2, g_c2);

    cudaFuncSetAttribute(attn_tc,
                         cudaFuncAttributeMaxDynamicSharedMemorySize, ATTN_SMEM);

    // 1) QKV projection + bias, scatter into q/k/v (k pre-scaled by 1/8)
    dim3 g1(3 * DM / 128, MROWS / 128);
    gemm_tc<1><<<g1, 256>>>(x, Ww, Wb, nullptr, MROWS, 3 * DM, DM, q, k, v);

    // 2-4) repeated causal attention
    dim3 ga(SEQ / 64, NH, BATCH);
    attn_tc<<<ga, 128, ATTN_SMEM>>>(q,  k, v, c1);
    attn_tc<<<ga, 128, ATTN_SMEM>>>(c1, k, v, c2);
    attn_tc<<<ga, 128, ATTN_SMEM>>>(c2, k, v, c1);

    // 5) output projection + bias
    dim3 g2(DM / 128, MROWS / 128);
    gemm_tc<0><<<g2, 256>>>(c1, Ow, Ob, out, MROWS, DM, DM,
                            nullptr, nullptr, nullptr);
}

// round 3
// speedup vs baseline: 3.1320x; 1.0133x over previous
#include <cuda_runtime.h>
#include <math.h>

#define DM    1024
#define NH    16
#define HD    64
#define BATCH 2
#define SEQ   2048
#define MROWS (BATCH*SEQ)      // 4096

// Scratch (device globals — no allocation allowed)
__device__ float g_q [MROWS*DM];
__device__ float g_k [MROWS*DM];   // pre-scaled by 1/sqrt(HD)
__device__ float g_v [MROWS*DM];
__device__ float g_c1[MROWS*DM];
__device__ float g_c2[MROWS*DM];

__device__ __forceinline__ unsigned f2tf(float f) {
    unsigned u;
    asm("cvt.rna.tf32.f32 %0, %1;" : "=r"(u) : "f"(f));
    return u;
}

__device__ __forceinline__ void mma8(float* d, const unsigned* a,
                                     unsigned b0, unsigned b1) {
    asm volatile(
        "mma.sync.aligned.m16n8k8.row.col.f32.tf32.tf32.f32 "
        "{%0,%1,%2,%3}, {%4,%5,%6,%7}, {%8,%9}, {%0,%1,%2,%3};"
        : "+f"(d[0]), "+f"(d[1]), "+f"(d[2]), "+f"(d[3])
        : "r"(a[0]), "r"(a[1]), "r"(a[2]), "r"(a[3]), "r"(b0), "r"(b1));
}

// ---------------------------------------------------------------------------
// TF32 tensor-core GEMM: C[M,N] = A[M,K] @ Bw[N,K]^T + bias[N]
// MODE 0: plain write; MODE 1: qkv scatter (k scaled by 0.125)
// CTA tile 128x128, 256 threads (8 warps 4x2), warp tile 32x64, kc=16.
// Software-pipelined: next k-chunk register-prefetched during current MMAs.
// ---------------------------------------------------------------------------
template<int MODE>
__global__ __launch_bounds__(256)
void gemm_tc(const float* __restrict__ A, const float* __restrict__ Bw,
             const float* __restrict__ bias, float* __restrict__ C,
             int M, int N, int K,
             float* __restrict__ qo, float* __restrict__ ko,
             float* __restrict__ vo)
{
    __shared__ unsigned As[128][20];
    __shared__ unsigned Bs[128][20];

    const int tid = threadIdx.x;
    const int wid = tid >> 5, lane = tid & 31;
    const int lg = lane >> 2, la3 = lane & 3;
    const int wm = wid & 3, wn = wid >> 2;          // warp grid 4x2
    const int bm = blockIdx.y * 128, bn = blockIdx.x * 128;

    float acc[2][8][4];
    #pragma unroll
    for (int mt = 0; mt < 2; mt++)
        #pragma unroll
        for (int nt = 0; nt < 8; nt++)
            #pragma unroll
            for (int i = 0; i < 4; i++) acc[mt][nt][i] = 0.f;

    const int lrow = tid >> 2, lcol = (tid & 3) * 4;   // 64 rows x 16 cols
    const float* Ap = A  + (size_t)(bm + lrow) * K + lcol;
    const float* Bp = Bw + (size_t)(bn + lrow) * K + lcol;

    // prefetch chunk 0
    float4 a0 = *(const float4*)(Ap);
    float4 a1 = *(const float4*)(Ap + (size_t)64 * K);
    float4 b0 = *(const float4*)(Bp);
    float4 b1 = *(const float4*)(Bp + (size_t)64 * K);

    for (int k0 = 0; k0 < K; k0 += 16) {
        __syncthreads();   // previous chunk's MMAs done reading smem
        *(uint4*)&As[lrow   ][lcol] = make_uint4(f2tf(a0.x), f2tf(a0.y), f2tf(a0.z), f2tf(a0.w));
        *(uint4*)&As[lrow+64][lcol] = make_uint4(f2tf(a1.x), f2tf(a1.y), f2tf(a1.z), f2tf(a1.w));
        *(uint4*)&Bs[lrow   ][lcol] = make_uint4(f2tf(b0.x), f2tf(b0.y), f2tf(b0.z), f2tf(b0.w));
        *(uint4*)&Bs[lrow+64][lcol] = make_uint4(f2tf(b1.x), f2tf(b1.y), f2tf(b1.z), f2tf(b1.w));
        if (k0 + 16 < K) {   // prefetch next chunk; latency hidden by MMAs
            a0 = *(const float4*)(Ap + k0 + 16);
            a1 = *(const float4*)(Ap + (size_t)64 * K + k0 + 16);
            b0 = *(const float4*)(Bp + k0 + 16);
            b1 = *(const float4*)(Bp + (size_t)64 * K + k0 + 16);
        }
        __syncthreads();

        #pragma unroll
        for (int ks = 0; ks < 2; ks++) {
            unsigned af[2][4], bf[8][2];
            #pragma unroll
            for (int mt = 0; mt < 2; mt++) {
                const int r = wm * 32 + mt * 16 + lg;
                af[mt][0] = As[r    ][ks * 8 + la3];
                af[mt][1] = As[r + 8][ks * 8 + la3];
                af[mt][2] = As[r    ][ks * 8 + la3 + 4];
                af[mt][3] = As[r + 8][ks * 8 + la3 + 4];
            }
            #pragma unroll
            for (int nt = 0; nt < 8; nt++) {
                const int n = wn * 64 + nt * 8 + lg;
                bf[nt][0] = Bs[n][ks * 8 + la3];
                bf[nt][1] = Bs[n][ks * 8 + la3 + 4];
            }
            #pragma unroll
            for (int mt = 0; mt < 2; mt++)
                #pragma unroll
                for (int nt = 0; nt < 8; nt++)
                    mma8(acc[mt][nt], af[mt], bf[nt][0], bf[nt][1]);
        }
    }

    #pragma unroll
    for (int mt = 0; mt < 2; mt++)
        #pragma unroll
        for (int nt = 0; nt < 8; nt++)
            #pragma unroll
            for (int i = 0; i < 4; i++) {
                const int row = bm + wm * 32 + mt * 16 + lg + (i >> 1) * 8;
                const int col = bn + wn * 64 + nt * 8 + 2 * la3 + (i & 1);
                float val = acc[mt][nt][i] + bias[col];
                if (MODE == 0) {
                    C[(size_t)row * N + col] = val;
                } else {
                    const int g   = col >> 10;
                    const int rem = col & 1023;
                    if (g == 1) val *= 0.125f;
                    float* dst = (g == 0) ? qo : (g == 1) ? ko : vo;
                    dst[(size_t)row * DM + rem] = val;
                }
            }
}

// ---------------------------------------------------------------------------
// TF32 tensor-core causal flash attention, software-pipelined staging.
// CTA: 128 threads (4 warps), 64-row Q tile.
//  - K tile for kt+1 register-prefetched during tile kt's compute
//  - V tile loads issued before S-MMA/softmax, stored after (latency hidden)
//  - Q kept in smem; fragments re-loaded per k8 (low reg pressure)
// ---------------------------------------------------------------------------
#define KP 68   // pad: bank = 4*lg+la3 -> conflict-free A/B frag loads
#define VP 72   // pad: bank = 8*la3+lg -> conflict-free PV-B frag loads
#define ATTN_SMEM ((64*KP + 64*KP + 64*VP + 64*KP) * 4)  // Qs,Ks,Vs,Ps

__global__ __launch_bounds__(128)
void attn_tc(const float* __restrict__ Qb, const float* __restrict__ Kb,
             const float* __restrict__ Vb, float* __restrict__ Ob)
{
    extern __shared__ unsigned sm[];
    unsigned (*Qs)[KP] = (unsigned(*)[KP])sm;                     // [64][68]
    unsigned (*Ks)[KP] = (unsigned(*)[KP])(sm + 64*KP);           // [64][68]
    unsigned (*Vs)[VP] = (unsigned(*)[VP])(sm + 2*64*KP);         // [64][72]
    unsigned (*Ps)[KP] = (unsigned(*)[KP])(sm + 2*64*KP + 64*VP); // [64][68]

    const int qt = (int)gridDim.x - 1 - (int)blockIdx.x;    // long rows first
    const int h = blockIdx.y, b = blockIdx.z;
    const int tid = threadIdx.x, wid = tid >> 5, lane = tid & 31;
    const int lg = lane >> 2, la3 = lane & 3;
    const int wb = wid * 16;
    const float NEG_INF = __int_as_float(0xff800000);

    const size_t base = (size_t)b * SEQ * DM + (size_t)h * HD;
    const int lr = tid >> 4, lc = (tid & 15) * 4;   // loader: 8 rows x 64 cols/iter

    // ---- Stage Q into Qs ----
    {
        const float* Qg = Qb + base + (size_t)(qt * 64) * DM;
        #pragma unroll
        for (int i = 0; i < 8; i++) {
            const int r = lr + i * 8;
            float4 v = *(const float4*)(Qg + (size_t)r * DM + lc);
            *(uint4*)&Qs[r][lc] = make_uint4(f2tf(v.x), f2tf(v.y), f2tf(v.z), f2tf(v.w));
        }
    }

    // ---- Prefetch K tile 0 ----
    float4 kr[8];
    {
        const float* Kg = Kb + base;
        #pragma unroll
        for (int i = 0; i < 8; i++)
            kr[i] = *(const float4*)(Kg + (size_t)(lr + i * 8) * DM + lc);
    }

    float m0 = NEG_INF, m1 = NEG_INF, l0 = 0.f, l1 = 0.f;
    float O[8][4];
    #pragma unroll
    for (int nt = 0; nt < 8; nt++)
        #pragma unroll
        for (int i = 0; i < 4; i++) O[nt][i] = 0.f;

    __syncthreads();   // Qs visible

    for (int kt = 0; kt <= qt; kt++) {
        if (kt) __syncthreads();   // barrier A: prev tile's MMAs done

        // store prefetched K -> Ks (cvt)
        #pragma unroll
        for (int i = 0; i < 8; i++)
            *(uint4*)&Ks[lr + i * 8][lc] =
                make_uint4(f2tf(kr[i].x), f2tf(kr[i].y), f2tf(kr[i].z), f2tf(kr[i].w));

        // issue V loads for THIS tile (consumed after softmax -> latency hidden)
        float4 vr[8];
        {
            const float* Vg = Vb + base + (size_t)(kt * 64) * DM;
            #pragma unroll
            for (int i = 0; i < 8; i++)
                vr[i] = *(const float4*)(Vg + (size_t)(lr + i * 8) * DM + lc);
        }
        // prefetch K for next tile (consumed next iteration)
        if (kt < qt) {
            const float* Kg = Kb + base + (size_t)((kt + 1) * 64) * DM;
            #pragma unroll
            for (int i = 0; i < 8; i++)
                kr[i] = *(const float4*)(Kg + (size_t)(lr + i * 8) * DM + lc);
        }
        __syncthreads();   // barrier B: Ks ready

        // ---- S = Q @ K^T (16x64 per warp) ----
        float S[8][4];
        #pragma unroll
        for (int nt = 0; nt < 8; nt++)
            #pragma unroll
            for (int i = 0; i < 4; i++) S[nt][i] = 0.f;

        #pragma unroll
        for (int k8 = 0; k8 < 8; k8++) {
            unsigned qf[4];
            qf[0] = Qs[wb + lg    ][k8 * 8 + la3];
            qf[1] = Qs[wb + lg + 8][k8 * 8 + la3];
            qf[2] = Qs[wb + lg    ][k8 * 8 + la3 + 4];
            qf[3] = Qs[wb + lg + 8][k8 * 8 + la3 + 4];
            #pragma unroll
            for (int nt = 0; nt < 8; nt++) {
                unsigned b0 = Ks[nt * 8 + lg][k8 * 8 + la3];
                unsigned b1 = Ks[nt * 8 + lg][k8 * 8 + la3 + 4];
                mma8(S[nt], qf, b0, b1);
            }
        }

        // ---- Causal mask (diagonal tile only) ----
        if (kt == qt) {
            #pragma unroll
            for (int nt = 0; nt < 8; nt++) {
                const int c0 = nt * 8 + 2 * la3;
                const int r0 = wb + lg, r1 = r0 + 8;
                if (c0     > r0) S[nt][0] = NEG_INF;
                if (c0 + 1 > r0) S[nt][1] = NEG_INF;
                if (c0     > r1) S[nt][2] = NEG_INF;
                if (c0 + 1 > r1) S[nt][3] = NEG_INF;
            }
        }

        // ---- Online softmax (rows r0, r1; 4-lane quads) ----
        float mx0 = NEG_INF, mx1 = NEG_INF;
        #pragma unroll
        for (int nt = 0; nt < 8; nt++) {
            mx0 = fmaxf(mx0, fmaxf(S[nt][0], S[nt][1]));
            mx1 = fmaxf(mx1, fmaxf(S[nt][2], S[nt][3]));
        }
        mx0 = fmaxf(mx0, __shfl_xor_sync(0xffffffffu, mx0, 1));
        mx0 = fmaxf(mx0, __shfl_xor_sync(0xffffffffu, mx0, 2));
        mx1 = fmaxf(mx1, __shfl_xor_sync(0xffffffffu, mx1, 1));
        mx1 = fmaxf(mx1, __shfl_xor_sync(0xffffffffu, mx1, 2));
        const float mn0 = fmaxf(m0, mx0), mn1 = fmaxf(m1, mx1);
        const float al0 = __expf(m0 - mn0), al1 = __expf(m1 - mn1);
        float rs0 = 0.f, rs1 = 0.f;
        #pragma unroll
        for (int nt = 0; nt < 8; nt++) {
            S[nt][0] = __expf(S[nt][0] - mn0);
            S[nt][1] = __expf(S[nt][1] - mn0);
            S[nt][2] = __expf(S[nt][2] - mn1);
            S[nt][3] = __expf(S[nt][3] - mn1);
            rs0 += S[nt][0] + S[nt][1];
            rs1 += S[nt][2] + S[nt][3];
        }
        rs0 += __shfl_xor_sync(0xffffffffu, rs0, 1);
        rs0 += __shfl_xor_sync(0xffffffffu, rs0, 2);
        rs1 += __shfl_xor_sync(0xffffffffu, rs1, 1);
        rs1 += __shfl_xor_sync(0xffffffffu, rs1, 2);
        l0 = l0 * al0 + rs0;  m0 = mn0;
        l1 = l1 * al1 + rs1;  m1 = mn1;
        #pragma unroll
        for (int nt = 0; nt < 8; nt++) {
            O[nt][0] *= al0;  O[nt][1] *= al0;
            O[nt][2] *= al1;  O[nt][3] *= al1;
        }

        // ---- P -> per-warp smem (layout fixup) ----
        #pragma unroll
        for (int nt = 0; nt < 8; nt++) {
            *(uint2*)&Ps[wb + lg    ][nt * 8 + 2 * la3] =
                make_uint2(f2tf(S[nt][0]), f2tf(S[nt][1]));
            *(uint2*)&Ps[wb + lg + 8][nt * 8 + 2 * la3] =
                make_uint2(f2tf(S[nt][2]), f2tf(S[nt][3]));
        }

        // ---- store V (loads issued pre-softmax, latency now drained) ----
        #pragma unroll
        for (int i = 0; i < 8; i++)
            *(uint4*)&Vs[lr + i * 8][lc] =
                make_uint4(f2tf(vr[i].x), f2tf(vr[i].y), f2tf(vr[i].z), f2tf(vr[i].w));
        __syncthreads();   // barrier C: Vs ready (also covers per-warp Ps)

        // ---- O += P @ V ----
        #pragma unroll
        for (int k8 = 0; k8 < 8; k8++) {
            unsigned pf[4];
            pf[0] = Ps[wb + lg    ][k8 * 8 + la3];
            pf[1] = Ps[wb + lg + 8][k8 * 8 + la3];
            pf[2] = Ps[wb + lg    ][k8 * 8 + la3 + 4];
            pf[3] = Ps[wb + lg + 8][k8 * 8 + la3 + 4];
            #pragma unroll
            for (int nt = 0; nt < 8; nt++) {
                unsigned b0 = Vs[k8 * 8 + la3    ][nt * 8 + lg];
                unsigned b1 = Vs[k8 * 8 + la3 + 4][nt * 8 + lg];
                mma8(O[nt], pf, b0, b1);
            }
        }
    }

    // ---- Epilogue ----
    float* Og = Ob + base + (size_t)(qt * 64) * DM;
    const float il0 = 1.0f / l0, il1 = 1.0f / l1;
    #pragma unroll
    for (int nt = 0; nt < 8; nt++) {
        const int col = nt * 8 + 2 * la3;
        *(float2*)(Og + (size_t)(wb + lg    ) * DM + col) =
            make_float2(O[nt][0] * il0, O[nt][1] * il0);
        *(float2*)(Og + (size_t)(wb + lg + 8) * DM + col) =
            make_float2(O[nt][2] * il1, O[nt][3] * il1);
    }
}

// ---------------------------------------------------------------------------
extern "C" void kernel_launch(void* const* d_in, const int* in_sizes, int n_in,
                              void* d_out, int out_size)
{
    const float* x  = (const float*)d_in[0];
    const float* Ww = (const float*)d_in[1];
    const float* Wb = (const float*)d_in[2];
    const float* Ow = (const float*)d_in[3];
    const float* Ob = (const float*)d_in[4];
    float* out = (float*)d_out;

    float *q, *k, *v, *c1, *c2;
    cudaGetSymbolAddress((void**)&q,  g_q);
    cudaGetSymbolAddress((void**)&k,  g_k);
    cudaGetSymbolAddress((void**)&v,  g_v);
    cudaGetSymbolAddress((void**)&c1, g_c1);
    cudaGetSymbolAddress((void**)&c2, g_c2);

    cudaFuncSetAttribute(attn_tc,
                         cudaFuncAttributeMaxDynamicSharedMemorySize, ATTN_SMEM);

    // 1) QKV projection + bias, scatter into q/k/v (k pre-scaled by 1/8)
    dim3 g1(3 * DM / 128, MROWS / 128);
    gemm_tc<1><<<g1, 256>>>(x, Ww, Wb, nullptr, MROWS, 3 * DM, DM, q, k, v);

    // 2-4) repeated causal attention
    dim3 ga(SEQ / 64, NH, BATCH);
    attn_tc<<<ga, 128, ATTN_SMEM>>>(q,  k, v, c1);
    attn_tc<<<ga, 128, ATTN_SMEM>>>(c1, k, v, c2);
    attn_tc<<<ga, 128, ATTN_SMEM>>>(c2, k, v, c1);

    // 5) output projection + bias
    dim3 g2(DM / 128, MROWS / 128);
    gemm_tc<0><<<g2, 256>>>(c1, Ow, Ob, out, MROWS, DM, DM,
                            nullptr, nullptr, nullptr);
}